// round 15
// baseline (speedup 1.0000x reference)
#include <cuda_runtime.h>

// ---------------- problem constants ----------------
constexpr int N_ATOMS = 4096;
constexpr int T_TOK   = 512;
constexpr int AS      = 128;   // atom_s
constexpr int AZ      = 16;    // atom_z
constexpr int TS      = 384;   // token_s
constexpr int FD      = 388;   // feat_dim

// ---------------- scratch (device globals; no allocation) ----------------
__device__ float g_s2c[T_TOK * AS];
__device__ float g_zp [T_TOK * T_TOK * AZ];            // 16.8 MB
__device__ float g_cqp[N_ATOMS * AZ];
__device__ float g_ckp[N_ATOMS * AZ];
__device__ unsigned long long g_wI[128 * 8];           // zp weights, z-pair interleaved
__device__ float g_A[16];
__device__ float g_B[16];
__device__ float g_swT[TS * AS];                       // s2c scale∘W, transposed [k][ch]
__device__ float g_A2[AS];
__device__ float g_B2[AS];

// ---------------- f32x2 / cp.async helpers ----------------
__device__ __forceinline__ unsigned long long ffma2(unsigned long long a,
                                                    unsigned long long b,
                                                    unsigned long long c)
{
    unsigned long long d;
    asm("fma.rn.f32x2 %0, %1, %2, %3;" : "=l"(d) : "l"(a), "l"(b), "l"(c));
    return d;
}
__device__ __forceinline__ unsigned long long pack2(float lo, float hi)
{
    unsigned long long d;
    asm("mov.b64 %0, {%1, %2};" : "=l"(d) : "f"(lo), "f"(hi));
    return d;
}
__device__ __forceinline__ void unpack2(unsigned long long v, float& lo, float& hi)
{
    asm("mov.b64 {%0, %1}, %2;" : "=f"(lo), "=f"(hi) : "l"(v));
}
__device__ __forceinline__ void cp16(unsigned int dst_smem, const void* src)
{
    asm volatile("cp.async.cg.shared.global [%0], [%1], 16;"
                 :: "r"(dst_smem), "l"(src));
}
#define CP_COMMIT() asm volatile("cp.async.commit_group;")
#define CP_WAIT(N)  asm volatile("cp.async.wait_group %0;" :: "n"(N))

// ============================================================
// Kernel 0 (v2): prep — zp weight fold + s2c weight fold/transpose
// ============================================================
__global__ void prep_kernel(const float* __restrict__ ln_z_s,
                            const float* __restrict__ ln_z_b,
                            const float* __restrict__ Wz,     // [16,128]
                            const float* __restrict__ ln_s_s,
                            const float* __restrict__ ln_s_b,
                            const float* __restrict__ Ws2c)   // [128,384]
{
    int b = blockIdx.x, tid = threadIdx.x;
    if (b < 128) {
        #pragma unroll
        for (int kk = 0; kk < 3; kk++) {
            int k = b * 3 + kk;
            g_swT[k * 128 + tid] = ln_s_s[k] * Ws2c[tid * TS + k];
        }
    } else if (b == 128) {
        float* wf = reinterpret_cast<float*>(g_wI);
        for (int i = tid; i < 2048; i += 128) {
            int k = i >> 4, p = (i >> 1) & 7, h = i & 1;
            wf[i] = ln_z_s[k] * Wz[(2 * p + h) * 128 + k];
        }
        if (tid < 16) {
            float a = 0.f, bb = 0.f;
            for (int l = 0; l < 128; l++) {
                float w = Wz[tid * 128 + l];
                a += ln_z_s[l] * w;
                bb += ln_z_b[l] * w;
            }
            g_A[tid] = a;
            g_B[tid] = bb;
        }
    } else {
        float a = 0.f, bb = 0.f;
        const float* wr = Ws2c + tid * TS;
        for (int k = 0; k < TS; k++) {
            float w = wr[k];
            a  = fmaf(ln_s_s[k], w, a);
            bb = fmaf(ln_s_b[k], w, bb);
        }
        g_A2[tid] = a;
        g_B2[tid] = bb;
    }
}

// ============================================================
// Kernel 1 (v2): s2c — LN folded into GEMM, 4 tokens/block,
//   256 threads, grid 128.
// ============================================================
__global__ void __launch_bounds__(256)
s2c_kernel(const float* __restrict__ s_trunk)
{
    __shared__ __align__(16) float xs[4 * TS];
    __shared__ float redA[8], redB[8];
    __shared__ float sM[4], sR[4];
    int tid = threadIdx.x;
    int t0  = blockIdx.x * 4;

    {
        const float4* src = reinterpret_cast<const float4*>(s_trunk) + t0 * 96;
        float4* dst = reinterpret_cast<float4*>(xs);
        for (int i = tid; i < 384; i += 256) dst[i] = src[i];
    }
    __syncthreads();

    {
        int t = tid >> 6, l = tid & 63;
        float s1 = 0.f, s2 = 0.f;
        #pragma unroll
        for (int j = 0; j < 6; j++) {
            float x = xs[t * TS + l * 6 + j];
            s1 += x; s2 = fmaf(x, x, s2);
        }
        #pragma unroll
        for (int o = 16; o >= 1; o >>= 1) {
            s1 += __shfl_xor_sync(~0u, s1, o);
            s2 += __shfl_xor_sync(~0u, s2, o);
        }
        if ((tid & 31) == 0) {
            redA[tid >> 5] = s1;
            redB[tid >> 5] = s2;
        }
    }
    __syncthreads();
    if (tid < 4) {
        float s1 = redA[2 * tid] + redA[2 * tid + 1];
        float s2 = redB[2 * tid] + redB[2 * tid + 1];
        float m    = s1 * (1.f / TS);
        float var  = s2 * (1.f / TS) - m * m;
        sM[tid] = m;
        sR[tid] = rsqrtf(var + 1e-5f);
    }
    __syncthreads();

    int ch = tid & 127;
    int tg = tid >> 7;
    const float* x0p = xs + (2 * tg) * TS;
    const float* x1p = xs + (2 * tg + 1) * TS;
    const float* wp  = g_swT + ch;

    unsigned long long accp = 0ULL;
    #pragma unroll 8
    for (int k = 0; k < TS; k++) {
        float w = wp[k * 128];
        unsigned long long xv = pack2(x0p[k], x1p[k]);
        accp = ffma2(xv, pack2(w, w), accp);
    }
    float d0, d1;
    unpack2(accp, d0, d1);
    float A2 = g_A2[ch], B2 = g_B2[ch];
    int ta = 2 * tg, tb = 2 * tg + 1;
    g_s2c[(t0 + ta) * AS + ch] = (d0 - sM[ta] * A2) * sR[ta] + B2;
    g_s2c[(t0 + tb) * AS + ch] = (d1 - sM[tb] * A2) * sR[tb] + B2;
}

// ============================================================
// Kernel 2 (v3, measured 40.0us): c = feats @ W^T + b —
//   weights in REGISTERS, 16 atoms/block, 128 threads.
// ============================================================
__global__ void __launch_bounds__(128)
c_kernel(const float* __restrict__ ref_pos,
         const float* __restrict__ ref_charge,
         const float* __restrict__ ref_element,
         const float* __restrict__ ref_chars,
         const float* __restrict__ W_feat,  // [128,388]
         const float* __restrict__ b_feat,
         const float* __restrict__ Wq16,    // [16,128]
         const float* __restrict__ Wk16,    // [16,128]
         const int*   __restrict__ uid,
         float* __restrict__ q_out,
         float* __restrict__ c_out)
{
    __shared__ __align__(16) float faI[388 * 20];   // 31.04 KB [k][atom16+pad4]
    int tid = threadIdx.x;
    int n0  = blockIdx.x * 16;

    for (int i = tid; i < 16 * 128; i += 128) {
        int a = i >> 7, e = i & 127;
        faI[(4 + e) * 20 + a] = ref_element[(n0 + a) * 128 + e];
    }
    for (int i = tid; i < 16 * 256; i += 128) {
        int a = i >> 8, e = i & 255;
        faI[(132 + e) * 20 + a] = ref_chars[(n0 + a) * 256 + e];
    }
    if (tid < 64) {
        int a = tid >> 2, cm = tid & 3;
        faI[cm * 20 + a] = (cm < 3) ? ref_pos[(n0 + a) * 3 + cm]
                                    : ref_charge[n0 + a];
    }

    const float* wrow = W_feat + tid * FD;
    float4 cw0 = *reinterpret_cast<const float4*>(wrow + 0);
    float4 cw1 = *reinterpret_cast<const float4*>(wrow + 4);
    float4 cw2 = *reinterpret_cast<const float4*>(wrow + 8);
    float4 cw3 = *reinterpret_cast<const float4*>(wrow + 12);

    unsigned long long accp[8];
    {
        float bj = b_feat[tid];
        unsigned long long bb = pack2(bj, bj);
        #pragma unroll
        for (int p = 0; p < 8; p++) accp[p] = bb;
    }
    __syncthreads();

    for (int ch = 0; ch < 24; ch++) {
        float wv[16] = {cw0.x, cw0.y, cw0.z, cw0.w,
                        cw1.x, cw1.y, cw1.z, cw1.w,
                        cw2.x, cw2.y, cw2.z, cw2.w,
                        cw3.x, cw3.y, cw3.z, cw3.w};
        if (ch < 23) {
            const float* nb = wrow + (ch + 1) * 16;
            cw0 = *reinterpret_cast<const float4*>(nb + 0);
            cw1 = *reinterpret_cast<const float4*>(nb + 4);
            cw2 = *reinterpret_cast<const float4*>(nb + 8);
            cw3 = *reinterpret_cast<const float4*>(nb + 12);
        }
        int kbase = ch * 16;
        #pragma unroll
        for (int kk = 0; kk < 16; kk++) {
            unsigned long long wp = pack2(wv[kk], wv[kk]);
            const ulonglong2* xr =
                reinterpret_cast<const ulonglong2*>(faI + (kbase + kk) * 20);
            #pragma unroll
            for (int p = 0; p < 4; p++) {
                ulonglong2 x2 = xr[p];
                accp[2 * p]     = ffma2(x2.x, wp, accp[2 * p]);
                accp[2 * p + 1] = ffma2(x2.y, wp, accp[2 * p + 1]);
            }
        }
    }
    {
        float4 wt = *reinterpret_cast<const float4*>(wrow + 384);
        float wv[4] = {wt.x, wt.y, wt.z, wt.w};
        #pragma unroll
        for (int j = 0; j < 4; j++) {
            unsigned long long wp = pack2(wv[j], wv[j]);
            const ulonglong2* xr =
                reinterpret_cast<const ulonglong2*>(faI + (384 + j) * 20);
            #pragma unroll
            for (int p = 0; p < 4; p++) {
                ulonglong2 x2 = xr[p];
                accp[2 * p]     = ffma2(x2.x, wp, accp[2 * p]);
                accp[2 * p + 1] = ffma2(x2.y, wp, accp[2 * p + 1]);
            }
        }
    }

    float cval[16];
    #pragma unroll
    for (int p = 0; p < 8; p++)
        unpack2(accp[p], cval[2 * p], cval[2 * p + 1]);
    #pragma unroll
    for (int a = 0; a < 16; a++) {
        int n = n0 + a;
        q_out[n * AS + tid] = cval[a];
        cval[a] += g_s2c[uid[n] * AS + tid];
        c_out[n * AS + tid] = cval[a];
    }
    __syncthreads();

    float* cs  = faI;
    float* wqk = faI + 2112;
    #pragma unroll
    for (int a = 0; a < 16; a++) cs[a * 132 + tid] = cval[a];
    for (int i = tid; i < 32 * 128; i += 128) {
        int rr = i >> 7, l = i & 127;
        wqk[rr * 132 + l] = (rr < 16) ? Wq16[rr * 128 + l]
                                      : Wk16[(rr - 16) * 128 + l];
    }
    __syncthreads();

    int a = tid >> 3, g = tid & 7;
    float o0 = 0.f, o1 = 0.f, o2 = 0.f, o3 = 0.f;
    for (int l = 0; l < 128; l++) {
        float x = fmaxf(cs[a * 132 + l], 0.f);
        o0 += x * wqk[(g     ) * 132 + l];
        o1 += x * wqk[(g +  8) * 132 + l];
        o2 += x * wqk[(g + 16) * 132 + l];
        o3 += x * wqk[(g + 24) * 132 + l];
    }
    int n = n0 + a;
    g_cqp[n * 16 + g]     = o0;
    g_cqp[n * 16 + g + 8] = o1;
    g_ckp[n * 16 + g]     = o2;
    g_ckp[n * 16 + g + 8] = o3;
}

// ============================================================
// Kernel 3 (v7): zp — 64 rows/block, 42 KB smem (5 blocks/SM),
//   cp.async 2-phase pipeline, 4-way k-split (warp == k-split),
//   weights from PRECOMPUTED g_wI (no in-block prep — R11's poison).
//   xs: element (r, 4g+c) at float index g*264 + ((r+g)&63)*4 + c
//   staging bank-group (3g+r) mod 8, load (2g+col) mod 8 — permutations.
// ============================================================
constexpr int ZP_XS   = 8448;                       // 32 * 264 floats
constexpr int ZP_SMEM = (ZP_XS + 2048 + 32) * 4;    // ~41.1 KB

__global__ void __launch_bounds__(128)
zp_kernel(const float* __restrict__ z)
{
    extern __shared__ __align__(16) float smem[];
    float*      xs  = smem;                          // staging, then combine
    ulonglong2* swI = reinterpret_cast<ulonglong2*>(smem + ZP_XS);  // 512
    float*      sA  = reinterpret_cast<float*>(swI + 512);
    float*      sB  = sA + 16;

    int tid = threadIdx.x;
    int rg  = tid & 31;
    int kh  = tid >> 5;                              // warp id == k-split

    // issue async staging: group A rows 0..31, group B rows 32..63
    const float4* src = reinterpret_cast<const float4*>(z) +
                        (size_t)blockIdx.x * 2048;
    unsigned int xs_base = (unsigned int)__cvta_generic_to_shared(xs);
    #pragma unroll
    for (int it = 0; it < 8; it++) {
        int i = it * 128 + tid;
        int r = i >> 5, g = i & 31;
        int col = (r + g) & 63;
        cp16(xs_base + (unsigned)(g * 264 + col * 4) * 4, src + i);
    }
    CP_COMMIT();
    #pragma unroll
    for (int it = 8; it < 16; it++) {
        int i = it * 128 + tid;
        int r = i >> 5, g = i & 31;
        int col = (r + g) & 63;
        cp16(xs_base + (unsigned)(g * 264 + col * 4) * 4, src + i);
    }
    CP_COMMIT();

    // weight copy (overlaps DMA) — from precomputed global
    {
        const ulonglong2* srcw = reinterpret_cast<const ulonglong2*>(g_wI);
        for (int i = tid; i < 512; i += 128) swI[i] = srcw[i];
        if (tid < 16) { sA[tid] = g_A[tid]; sB[tid] = g_B[tid]; }
    }

    unsigned long long acc0[8], acc1[8];
    float s1a = 0.f, s2a = 0.f, s1b = 0.f, s2b = 0.f;
    #pragma unroll
    for (int p = 0; p < 8; p++) { acc0[p] = 0ULL; acc1[p] = 0ULL; }

    // phase A: rows 0..31
    CP_WAIT(1);
    __syncthreads();
    #pragma unroll 2
    for (int gi = 0; gi < 8; gi++) {
        int g = kh * 8 + gi;
        int col = (rg + g) & 63;
        float4 xv = *reinterpret_cast<const float4*>(xs + g * 264 + col * 4);
        float xarr[4] = {xv.x, xv.y, xv.z, xv.w};
        #pragma unroll
        for (int c = 0; c < 4; c++) {
            float x = xarr[c];
            s1a += x; s2a = fmaf(x, x, s2a);
            unsigned long long xp = pack2(x, x);
            const ulonglong2* wr = swI + (4 * g + c) * 4;
            #pragma unroll
            for (int q = 0; q < 4; q++) {
                ulonglong2 w2 = wr[q];
                acc0[2 * q]     = ffma2(xp, w2.x, acc0[2 * q]);
                acc0[2 * q + 1] = ffma2(xp, w2.y, acc0[2 * q + 1]);
            }
        }
    }

    // phase B: rows 32..63
    CP_WAIT(0);
    __syncthreads();
    #pragma unroll 2
    for (int gi = 0; gi < 8; gi++) {
        int g = kh * 8 + gi;
        int col = (rg + 32 + g) & 63;
        float4 xv = *reinterpret_cast<const float4*>(xs + g * 264 + col * 4);
        float xarr[4] = {xv.x, xv.y, xv.z, xv.w};
        #pragma unroll
        for (int c = 0; c < 4; c++) {
            float x = xarr[c];
            s1b += x; s2b = fmaf(x, x, s2b);
            unsigned long long xp = pack2(x, x);
            const ulonglong2* wr = swI + (4 * g + c) * 4;
            #pragma unroll
            for (int q = 0; q < 4; q++) {
                ulonglong2 w2 = wr[q];
                acc1[2 * q]     = ffma2(xp, w2.x, acc1[2 * q]);
                acc1[2 * q + 1] = ffma2(xp, w2.y, acc1[2 * q + 1]);
            }
        }
    }
    __syncthreads();   // xs reads done; reuse as combine buffer

    // combine 4 k-split partials (20-float slots, 5-float4 stride: conflict-free)
    if (kh > 0) {
        int idx = (kh - 1) * 32 + rg;
        #pragma unroll
        for (int c = 0; c < 2; c++) {
            unsigned long long* ac = c ? acc1 : acc0;
            float t[16];
            #pragma unroll
            for (int p = 0; p < 8; p++) unpack2(ac[p], t[2 * p], t[2 * p + 1]);
            float* bb = xs + c * 1920 + idx * 20;
            #pragma unroll
            for (int j = 0; j < 4; j++)
                *reinterpret_cast<float4*>(bb + 4 * j) =
                    make_float4(t[4*j], t[4*j+1], t[4*j+2], t[4*j+3]);
            bb[16] = c ? s1b : s1a;
            bb[17] = c ? s2b : s2a;
        }
    }
    __syncthreads();

    if (kh == 0) {
        #pragma unroll
        for (int c = 0; c < 2; c++) {
            unsigned long long* ac = c ? acc1 : acc0;
            float o[16];
            #pragma unroll
            for (int p = 0; p < 8; p++) unpack2(ac[p], o[2 * p], o[2 * p + 1]);
            float t1 = c ? s1b : s1a;
            float t2 = c ? s2b : s2a;
            #pragma unroll
            for (int w = 0; w < 3; w++) {
                const float* bb = xs + c * 1920 + (w * 32 + rg) * 20;
                #pragma unroll
                for (int j = 0; j < 4; j++) {
                    float4 pv = *reinterpret_cast<const float4*>(bb + 4 * j);
                    o[4*j+0] += pv.x; o[4*j+1] += pv.y;
                    o[4*j+2] += pv.z; o[4*j+3] += pv.w;
                }
                t1 += bb[16];
                t2 += bb[17];
            }
            float m    = t1 * (1.f / 128.f);
            float var  = t2 * (1.f / 128.f) - m * m;
            float rstd = rsqrtf(var + 1e-5f);

            size_t row = (size_t)blockIdx.x * 64 + 32 * c + rg;
            float* dst = g_zp + row * 16;
            #pragma unroll
            for (int j = 0; j < 4; j++) {
                float4 ov;
                ov.x = (o[4*j+0] - m * sA[4*j+0]) * rstd + sB[4*j+0];
                ov.y = (o[4*j+1] - m * sA[4*j+1]) * rstd + sB[4*j+1];
                ov.z = (o[4*j+2] - m * sA[4*j+2]) * rstd + sB[4*j+2];
                ov.w = (o[4*j+3] - m * sA[4*j+3]) * rstd + sB[4*j+3];
                *reinterpret_cast<float4*>(dst + 4 * j) = ov;
            }
        }
    }
}

// ============================================================
// Kernel 4: pairs — 2 queries per block share gathers + weight LDS
// ============================================================
__global__ void __launch_bounds__(128)
pairs_kernel(const float* __restrict__ ref_pos,
             const int*   __restrict__ uid,
             const float* __restrict__ Wp,   // [16,3]
             const float* __restrict__ Wd,   // [16]
             const float* __restrict__ Wm,   // [16]
             const float* __restrict__ W1,
             const float* __restrict__ W2,
             const float* __restrict__ W3,
             float* __restrict__ p_out)
{
    __shared__ __align__(16) float sWi[3][256];
    __shared__ float sWp[64], sWd[16], sWm[16];
    __shared__ float sCq[2][16];
    __shared__ float sPq[2][4];
    __shared__ int   sUq[2];
    int tid = threadIdx.x;
    int nq0 = blockIdx.x * 2;
    int nq1 = nq0 + 1;

    {
        int i = tid;
        #pragma unroll
        for (int it = 0; it < 2; it++, i += 128) {
            int j = i >> 4, op = (i >> 1) & 7, h = i & 1;
            int srcIdx = (2 * op + h) * 16 + j;
            sWi[0][i] = W1[srcIdx];
            sWi[1][i] = W2[srcIdx];
            sWi[2][i] = W3[srcIdx];
        }
    }
    if (tid < 16) {
        sWd[tid] = Wd[tid]; sWm[tid] = Wm[tid];
        sCq[0][tid] = g_cqp[nq0 * 16 + tid];
        sCq[1][tid] = g_cqp[nq1 * 16 + tid];
        sWp[tid * 4 + 0] = Wp[tid * 3 + 0];
        sWp[tid * 4 + 1] = Wp[tid * 3 + 1];
        sWp[tid * 4 + 2] = Wp[tid * 3 + 2];
    }
    if (tid < 2) {
        int nq = nq0 + tid;
        sUq[tid] = uid[nq];
        sPq[tid][0] = ref_pos[nq * 3 + 0];
        sPq[tid][1] = ref_pos[nq * 3 + 1];
        sPq[tid][2] = ref_pos[nq * 3 + 2];
    }
    __syncthreads();

    int khat = nq0 >> 5;
    int nk = 32 * khat - 48 + tid;
    bool valid = (nk >= 0) && (nk < N_ATOMS);

    int uq0 = sUq[0], uq1 = sUq[1];

    float acc0[16], acc1[16];
    #pragma unroll
    for (int zi = 0; zi < 16; zi++) { acc0[zi] = sCq[0][zi]; acc1[zi] = sCq[1][zi]; }

    if (valid) {
        int uk = uid[nk];
        const float4* zr0 = reinterpret_cast<const float4*>(
            g_zp + ((size_t)uq0 * 512 + uk) * 16);
        const float4* cr = reinterpret_cast<const float4*>(g_ckp + nk * 16);
        float zc0[16];
        #pragma unroll
        for (int j = 0; j < 4; j++) {
            float4 zv = zr0[j], cv = cr[j];
            zc0[4*j+0] = zv.x + cv.x; zc0[4*j+1] = zv.y + cv.y;
            zc0[4*j+2] = zv.z + cv.z; zc0[4*j+3] = zv.w + cv.w;
        }
        #pragma unroll
        for (int zi = 0; zi < 16; zi++) acc0[zi] += zc0[zi];
        if (uq1 == uq0) {
            #pragma unroll
            for (int zi = 0; zi < 16; zi++) acc1[zi] += zc0[zi];
        } else {
            const float4* zr1 = reinterpret_cast<const float4*>(
                g_zp + ((size_t)uq1 * 512 + uk) * 16);
            #pragma unroll
            for (int j = 0; j < 4; j++) {
                float4 zv = zr1[j], cv = cr[j];
                acc1[4*j+0] += zv.x + cv.x; acc1[4*j+1] += zv.y + cv.y;
                acc1[4*j+2] += zv.z + cv.z; acc1[4*j+3] += zv.w + cv.w;
            }
        }
        float px = ref_pos[nk * 3 + 0];
        float py = ref_pos[nk * 3 + 1];
        float pz = ref_pos[nk * 3 + 2];
        if (uk == uq0) {
            float dx = px - sPq[0][0], dy = py - sPq[0][1], dz = pz - sPq[0][2];
            float dn = 1.f / (1.f + dx * dx + dy * dy + dz * dz);
            #pragma unroll
            for (int zi = 0; zi < 16; zi++)
                acc0[zi] += sWp[zi*4+0]*dx + sWp[zi*4+1]*dy
                          + sWp[zi*4+2]*dz + sWd[zi]*dn + sWm[zi];
        }
        if (uk == uq1) {
            float dx = px - sPq[1][0], dy = py - sPq[1][1], dz = pz - sPq[1][2];
            float dn = 1.f / (1.f + dx * dx + dy * dy + dz * dz);
            #pragma unroll
            for (int zi = 0; zi < 16; zi++)
                acc1[zi] += sWp[zi*4+0]*dx + sWp[zi*4+1]*dy
                          + sWp[zi*4+2]*dz + sWd[zi]*dn + sWm[zi];
        }
    }

    unsigned long long h0[8], h1[8], g0[8], g1[8];

    #pragma unroll
    for (int p = 0; p < 8; p++) { h0[p] = 0ULL; h1[p] = 0ULL; }
    #pragma unroll
    for (int j = 0; j < 16; j++) {
        float t0 = fmaxf(acc0[j], 0.f), t1 = fmaxf(acc1[j], 0.f);
        unsigned long long xp0 = pack2(t0, t0), xp1 = pack2(t1, t1);
        const ulonglong2* wr = reinterpret_cast<const ulonglong2*>(sWi[0]) + j * 4;
        #pragma unroll
        for (int q = 0; q < 4; q++) {
            ulonglong2 w2 = wr[q];
            h0[2*q]   = ffma2(xp0, w2.x, h0[2*q]);
            h0[2*q+1] = ffma2(xp0, w2.y, h0[2*q+1]);
            h1[2*q]   = ffma2(xp1, w2.x, h1[2*q]);
            h1[2*q+1] = ffma2(xp1, w2.y, h1[2*q+1]);
        }
    }
    #pragma unroll
    for (int p = 0; p < 8; p++) { g0[p] = 0ULL; g1[p] = 0ULL; }
    #pragma unroll
    for (int p = 0; p < 8; p++) {
        float a0, a1, b0, b1;
        unpack2(h0[p], a0, a1); unpack2(h1[p], b0, b1);
        a0 = fmaxf(a0, 0.f); a1 = fmaxf(a1, 0.f);
        b0 = fmaxf(b0, 0.f); b1 = fmaxf(b1, 0.f);
        unsigned long long xa0 = pack2(a0, a0), xa1 = pack2(a1, a1);
        unsigned long long xb0 = pack2(b0, b0), xb1 = pack2(b1, b1);
        const ulonglong2* wr0 = reinterpret_cast<const ulonglong2*>(sWi[1]) + (2*p) * 4;
        const ulonglong2* wr1 = wr0 + 4;
        #pragma unroll
        for (int q = 0; q < 4; q++) {
            ulonglong2 wA = wr0[q];
            g0[2*q]   = ffma2(xa0, wA.x, g0[2*q]);
            g0[2*q+1] = ffma2(xa0, wA.y, g0[2*q+1]);
            g1[2*q]   = ffma2(xb0, wA.x, g1[2*q]);
            g1[2*q+1] = ffma2(xb0, wA.y, g1[2*q+1]);
            ulonglong2 wB = wr1[q];
            g0[2*q]   = ffma2(xa1, wB.x, g0[2*q]);
            g0[2*q+1] = ffma2(xa1, wB.y, g0[2*q+1]);
            g1[2*q]   = ffma2(xb1, wB.x, g1[2*q]);
            g1[2*q+1] = ffma2(xb1, wB.y, g1[2*q+1]);
        }
    }
    #pragma unroll
    for (int p = 0; p < 8; p++) { h0[p] = 0ULL; h1[p] = 0ULL; }
    #pragma unroll
    for (int p = 0; p < 8; p++) {
        float a0, a1, b0, b1;
        unpack2(g0[p], a0, a1); unpack2(g1[p], b0, b1);
        a0 = fmaxf(a0, 0.f); a1 = fmaxf(a1, 0.f);
        b0 = fmaxf(b0, 0.f); b1 = fmaxf(b1, 0.f);
        unsigned long long xa0 = pack2(a0, a0), xa1 = pack2(a1, a1);
        unsigned long long xb0 = pack2(b0, b0), xb1 = pack2(b1, b1);
        const ulonglong2* wr0 = reinterpret_cast<const ulonglong2*>(sWi[2]) + (2*p) * 4;
        const ulonglong2* wr1 = wr0 + 4;
        #pragma unroll
        for (int q = 0; q < 4; q++) {
            ulonglong2 wA = wr0[q];
            h0[2*q]   = ffma2(xa0, wA.x, h0[2*q]);
            h0[2*q+1] = ffma2(xa0, wA.y, h0[2*q+1]);
            h1[2*q]   = ffma2(xb0, wA.x, h1[2*q]);
            h1[2*q+1] = ffma2(xb0, wA.y, h1[2*q+1]);
            ulonglong2 wB = wr1[q];
            h0[2*q]   = ffma2(xa1, wB.x, h0[2*q]);
            h0[2*q+1] = ffma2(xa1, wB.y, h0[2*q+1]);
            h1[2*q]   = ffma2(xb1, wB.x, h1[2*q]);
            h1[2*q+1] = ffma2(xb1, wB.y, h1[2*q+1]);
        }
    }
    #pragma unroll
    for (int p = 0; p < 8; p++) {
        float lo, hi;
        unpack2(h0[p], lo, hi);
        acc0[2*p] += lo; acc0[2*p+1] += hi;
        unpack2(h1[p], lo, hi);
        acc1[2*p] += lo; acc1[2*p+1] += hi;
    }

    float* dst0 = p_out + ((size_t)nq0 * 128 + tid) * 16;
    float* dst1 = p_out + ((size_t)nq1 * 128 + tid) * 16;
    #pragma unroll
    for (int j = 0; j < 4; j++) {
        *reinterpret_cast<float4*>(dst0 + 4*j) =
            make_float4(acc0[4*j], acc0[4*j+1], acc0[4*j+2], acc0[4*j+3]);
        *reinterpret_cast<float4*>(dst1 + 4*j) =
            make_float4(acc1[4*j], acc1[4*j+1], acc1[4*j+2], acc1[4*j+3]);
    }
}

// ============================================================
extern "C" void kernel_launch(void* const* d_in, const int* in_sizes, int n_in,
                              void* d_out, int out_size)
{
    const float* ref_pos     = (const float*)d_in[0];
    const float* ref_charge  = (const float*)d_in[1];
    const float* ref_element = (const float*)d_in[2];
    const float* ref_chars   = (const float*)d_in[3];
    const float* s_trunk     = (const float*)d_in[5];
    const float* z           = (const float*)d_in[6];
    const float* W_feat      = (const float*)d_in[7];
    const float* b_feat      = (const float*)d_in[8];
    const float* W_rp        = (const float*)d_in[9];
    const float* W_rd        = (const float*)d_in[10];
    const float* W_msk       = (const float*)d_in[11];
    const float* ln_s_s      = (const float*)d_in[12];
    const float* ln_s_b      = (const float*)d_in[13];
    const float* W_s2c       = (const float*)d_in[14];
    const float* ln_z_s      = (const float*)d_in[15];
    const float* ln_z_b      = (const float*)d_in[16];
    const float* W_z2p       = (const float*)d_in[17];
    const float* W_cq        = (const float*)d_in[18];
    const float* W_ck        = (const float*)d_in[19];
    const float* W1          = (const float*)d_in[20];
    const float* W2          = (const float*)d_in[21];
    const float* W3          = (const float*)d_in[22];
    const int*   uid         = (const int*)d_in[24];

    float* out   = (float*)d_out;
    float* q_out = out;
    float* c_out = out + (size_t)N_ATOMS * AS;
    float* p_out = out + (size_t)2 * N_ATOMS * AS;

    static cudaStream_t s_side = nullptr;
    static cudaEvent_t  e_fork = nullptr, e_join = nullptr;
    static bool s_init = false;
    if (!s_init) {
        s_init = true;
        if (cudaStreamCreateWithFlags(&s_side, cudaStreamNonBlocking) != cudaSuccess)
            s_side = nullptr;
        if (s_side) {
            if (cudaEventCreateWithFlags(&e_fork, cudaEventDisableTiming) != cudaSuccess ||
                cudaEventCreateWithFlags(&e_join, cudaEventDisableTiming) != cudaSuccess) {
                s_side = nullptr;
            }
        }
    }
    cudaFuncSetAttribute(zp_kernel,
                         cudaFuncAttributeMaxDynamicSharedMemorySize, ZP_SMEM);

    bool overlap = (s_side != nullptr);
    cudaStream_t sc = overlap ? s_side : (cudaStream_t)0;

    // #1: prep on stream 0
    prep_kernel<<<130, 128>>>(ln_z_s, ln_z_b, W_z2p, ln_s_s, ln_s_b, W_s2c);
    if (overlap) {
        cudaEventRecord(e_fork, 0);
        cudaStreamWaitEvent(sc, e_fork, 0);
    }
    // #2 s2c, #3 c (side) ; #4 zp (s0 — profiled)
    s2c_kernel <<<T_TOK / 4, 256, 0, sc>>>(s_trunk);
    c_kernel   <<<N_ATOMS / 16, 128, 0, sc>>>(ref_pos, ref_charge, ref_element,
                                              ref_chars, W_feat, b_feat,
                                              W_cq, W_ck, uid, q_out, c_out);
    zp_kernel  <<<T_TOK * T_TOK / 64, 128, ZP_SMEM>>>(z);
    if (overlap) {
        cudaEventRecord(e_join, sc);
        cudaStreamWaitEvent(0, e_join, 0);
    }
    // #5: pairs
    pairs_kernel<<<N_ATOMS / 2, 128>>>(ref_pos, uid, W_rp, W_rd, W_msk,
                                       W1, W2, W3, p_out);
    (void)in_sizes; (void)n_in; (void)out_size;
}

// round 16
// speedup vs baseline: 1.4923x; 1.4923x over previous
#include <cuda_runtime.h>

// ---------------- problem constants ----------------
constexpr int N_ATOMS = 4096;
constexpr int T_TOK   = 512;
constexpr int AS      = 128;   // atom_s
constexpr int AZ      = 16;    // atom_z
constexpr int TS      = 384;   // token_s
constexpr int FD      = 388;   // feat_dim

// ---------------- scratch (device globals; no allocation) ----------------
__device__ float g_s2c[T_TOK * AS];
__device__ float g_zp [T_TOK * T_TOK * AZ];            // 16.8 MB
__device__ float g_cqp[N_ATOMS * AZ];
__device__ float g_ckp[N_ATOMS * AZ];
__device__ unsigned long long g_wI[128 * 8];           // zp weights, z-pair interleaved
__device__ float g_A[16];
__device__ float g_B[16];

// ---------------- f32x2 helpers ----------------
__device__ __forceinline__ unsigned long long ffma2(unsigned long long a,
                                                    unsigned long long b,
                                                    unsigned long long c)
{
    unsigned long long d;
    asm("fma.rn.f32x2 %0, %1, %2, %3;" : "=l"(d) : "l"(a), "l"(b), "l"(c));
    return d;
}
__device__ __forceinline__ unsigned long long pack2(float lo, float hi)
{
    unsigned long long d;
    asm("mov.b64 %0, {%1, %2};" : "=l"(d) : "f"(lo), "f"(hi));
    return d;
}
__device__ __forceinline__ void unpack2(unsigned long long v, float& lo, float& hi)
{
    asm("mov.b64 {%0, %1}, %2;" : "=f"(lo), "=f"(hi) : "l"(v));
}

// ============================================================
// Kernel 0 (v1): prep — fold LN scale into W_z_to_p, pair-interleave
// ============================================================
__global__ void prep_kernel(const float* __restrict__ ln_scale,
                            const float* __restrict__ ln_bias,
                            const float* __restrict__ Wz)   // [16,128]
{
    int tid = threadIdx.x;
    float* wf = reinterpret_cast<float*>(g_wI);
    for (int i = tid; i < 2048; i += 128) {
        int k = i >> 4, p = (i >> 1) & 7, h = i & 1;
        wf[i] = ln_scale[k] * Wz[(2 * p + h) * 128 + k];
    }
    if (tid < 16) {
        float a = 0.f, b = 0.f;
        for (int l = 0; l < 128; l++) {
            float w = Wz[tid * 128 + l];
            a += ln_scale[l] * w;
            b += ln_bias[l] * w;
        }
        g_A[tid] = a;
        g_B[tid] = b;
    }
}

// ============================================================
// Kernel 1 (v1): s2c[t][j] = LN(s_trunk[t]) @ W_s_to_c^T  (4 tokens/block)
// ============================================================
__global__ void s2c_kernel(const float* __restrict__ s_trunk,
                           const float* __restrict__ ln_scale,
                           const float* __restrict__ ln_bias,
                           const float* __restrict__ W)   // [128,384]
{
    __shared__ float xn[4 * 388];
    __shared__ float wc[32 * 132];
    int tid = threadIdx.x;
    int t0  = blockIdx.x * 4;

    for (int i = tid; i < 4 * TS; i += 128) {
        int r = i / TS, k = i - r * TS;
        xn[r * 388 + k] = s_trunk[(t0 + r) * TS + k];
    }
    __syncthreads();

    int r = tid >> 5, s = tid & 31;
    float s1 = 0.f, s2 = 0.f;
    for (int k = s * 12; k < s * 12 + 12; k++) {
        float x = xn[r * 388 + k]; s1 += x; s2 += x * x;
    }
    #pragma unroll
    for (int o = 16; o >= 1; o >>= 1) {
        s1 += __shfl_xor_sync(~0u, s1, o);
        s2 += __shfl_xor_sync(~0u, s2, o);
    }
    float m    = s1 * (1.f / TS);
    float var  = s2 * (1.f / TS) - m * m;
    float rstd = rsqrtf(var + 1e-5f);
    for (int k = s * 12; k < s * 12 + 12; k++) {
        float x = xn[r * 388 + k];
        xn[r * 388 + k] = (x - m) * rstd * ln_scale[k] + ln_bias[k];
    }
    __syncthreads();

    float acc[4] = {0.f, 0.f, 0.f, 0.f};
    for (int k0 = 0; k0 < TS; k0 += 32) {
        const float4* wr = reinterpret_cast<const float4*>(W + tid * TS + k0);
        #pragma unroll
        for (int q = 0; q < 8; q++) {
            float4 w4 = wr[q];
            wc[(q * 4 + 0) * 132 + tid] = w4.x;
            wc[(q * 4 + 1) * 132 + tid] = w4.y;
            wc[(q * 4 + 2) * 132 + tid] = w4.z;
            wc[(q * 4 + 3) * 132 + tid] = w4.w;
        }
        __syncthreads();
        #pragma unroll
        for (int kk = 0; kk < 32; kk += 4) {
            float w0 = wc[(kk + 0) * 132 + tid];
            float w1 = wc[(kk + 1) * 132 + tid];
            float w2 = wc[(kk + 2) * 132 + tid];
            float w3 = wc[(kk + 3) * 132 + tid];
            #pragma unroll
            for (int a = 0; a < 4; a++) {
                float4 x4 = *reinterpret_cast<const float4*>(&xn[a * 388 + k0 + kk]);
                acc[a] += x4.x * w0 + x4.y * w1 + x4.z * w2 + x4.w * w3;
            }
        }
        __syncthreads();
    }
    #pragma unroll
    for (int a = 0; a < 4; a++)
        g_s2c[(t0 + a) * AS + tid] = acc[a];
}

// ============================================================
// Kernel 2 (v3, measured 40.0us): c = feats @ W^T + b —
//   weights in REGISTERS, 16 atoms/block, 128 threads.
// ============================================================
__global__ void __launch_bounds__(128)
c_kernel(const float* __restrict__ ref_pos,
         const float* __restrict__ ref_charge,
         const float* __restrict__ ref_element,
         const float* __restrict__ ref_chars,
         const float* __restrict__ W_feat,  // [128,388]
         const float* __restrict__ b_feat,
         const float* __restrict__ Wq16,    // [16,128]
         const float* __restrict__ Wk16,    // [16,128]
         const int*   __restrict__ uid,
         float* __restrict__ q_out,
         float* __restrict__ c_out)
{
    __shared__ __align__(16) float faI[388 * 20];   // 31.04 KB [k][atom16+pad4]
    int tid = threadIdx.x;
    int n0  = blockIdx.x * 16;

    for (int i = tid; i < 16 * 128; i += 128) {
        int a = i >> 7, e = i & 127;
        faI[(4 + e) * 20 + a] = ref_element[(n0 + a) * 128 + e];
    }
    for (int i = tid; i < 16 * 256; i += 128) {
        int a = i >> 8, e = i & 255;
        faI[(132 + e) * 20 + a] = ref_chars[(n0 + a) * 256 + e];
    }
    if (tid < 64) {
        int a = tid >> 2, cm = tid & 3;
        faI[cm * 20 + a] = (cm < 3) ? ref_pos[(n0 + a) * 3 + cm]
                                    : ref_charge[n0 + a];
    }

    const float* wrow = W_feat + tid * FD;
    float4 cw0 = *reinterpret_cast<const float4*>(wrow + 0);
    float4 cw1 = *reinterpret_cast<const float4*>(wrow + 4);
    float4 cw2 = *reinterpret_cast<const float4*>(wrow + 8);
    float4 cw3 = *reinterpret_cast<const float4*>(wrow + 12);

    unsigned long long accp[8];
    {
        float bj = b_feat[tid];
        unsigned long long bb = pack2(bj, bj);
        #pragma unroll
        for (int p = 0; p < 8; p++) accp[p] = bb;
    }
    __syncthreads();

    for (int ch = 0; ch < 24; ch++) {
        float wv[16] = {cw0.x, cw0.y, cw0.z, cw0.w,
                        cw1.x, cw1.y, cw1.z, cw1.w,
                        cw2.x, cw2.y, cw2.z, cw2.w,
                        cw3.x, cw3.y, cw3.z, cw3.w};
        if (ch < 23) {
            const float* nb = wrow + (ch + 1) * 16;
            cw0 = *reinterpret_cast<const float4*>(nb + 0);
            cw1 = *reinterpret_cast<const float4*>(nb + 4);
            cw2 = *reinterpret_cast<const float4*>(nb + 8);
            cw3 = *reinterpret_cast<const float4*>(nb + 12);
        }
        int kbase = ch * 16;
        #pragma unroll
        for (int kk = 0; kk < 16; kk++) {
            unsigned long long wp = pack2(wv[kk], wv[kk]);
            const ulonglong2* xr =
                reinterpret_cast<const ulonglong2*>(faI + (kbase + kk) * 20);
            #pragma unroll
            for (int p = 0; p < 4; p++) {
                ulonglong2 x2 = xr[p];
                accp[2 * p]     = ffma2(x2.x, wp, accp[2 * p]);
                accp[2 * p + 1] = ffma2(x2.y, wp, accp[2 * p + 1]);
            }
        }
    }
    {
        float4 wt = *reinterpret_cast<const float4*>(wrow + 384);
        float wv[4] = {wt.x, wt.y, wt.z, wt.w};
        #pragma unroll
        for (int j = 0; j < 4; j++) {
            unsigned long long wp = pack2(wv[j], wv[j]);
            const ulonglong2* xr =
                reinterpret_cast<const ulonglong2*>(faI + (384 + j) * 20);
            #pragma unroll
            for (int p = 0; p < 4; p++) {
                ulonglong2 x2 = xr[p];
                accp[2 * p]     = ffma2(x2.x, wp, accp[2 * p]);
                accp[2 * p + 1] = ffma2(x2.y, wp, accp[2 * p + 1]);
            }
        }
    }

    float cval[16];
    #pragma unroll
    for (int p = 0; p < 8; p++)
        unpack2(accp[p], cval[2 * p], cval[2 * p + 1]);
    #pragma unroll
    for (int a = 0; a < 16; a++) {
        int n = n0 + a;
        q_out[n * AS + tid] = cval[a];
        cval[a] += g_s2c[uid[n] * AS + tid];
        c_out[n * AS + tid] = cval[a];
    }
    __syncthreads();

    float* cs  = faI;
    float* wqk = faI + 2112;
    #pragma unroll
    for (int a = 0; a < 16; a++) cs[a * 132 + tid] = cval[a];
    for (int i = tid; i < 32 * 128; i += 128) {
        int rr = i >> 7, l = i & 127;
        wqk[rr * 132 + l] = (rr < 16) ? Wq16[rr * 128 + l]
                                      : Wk16[(rr - 16) * 128 + l];
    }
    __syncthreads();

    int a = tid >> 3, g = tid & 7;
    float o0 = 0.f, o1 = 0.f, o2 = 0.f, o3 = 0.f;
    for (int l = 0; l < 128; l++) {
        float x = fmaxf(cs[a * 132 + l], 0.f);
        o0 += x * wqk[(g     ) * 132 + l];
        o1 += x * wqk[(g +  8) * 132 + l];
        o2 += x * wqk[(g + 16) * 132 + l];
        o3 += x * wqk[(g + 24) * 132 + l];
    }
    int n = n0 + a;
    g_cqp[n * 16 + g]     = o0;
    g_cqp[n * 16 + g + 8] = o1;
    g_ckp[n * 16 + g]     = o2;
    g_ckp[n * 16 + g + 8] = o3;
}

// ============================================================
// Kernel 3 (v5, measured 50.9us): zp — 128 rows/block,
//   4 rows/thread, 4-way k-split with warp == k-split.
// ============================================================
constexpr int ZP_XS_FLOATS = 16640;
constexpr int ZP_SMEM = ZP_XS_FLOATS * 4 + 512 * 16 + 2 * 16 * 4;  // ~74.8 KB

__global__ void __launch_bounds__(128)
zp_kernel(const float* __restrict__ z)
{
    extern __shared__ __align__(16) float smem[];
    float*      xs  = smem;
    ulonglong2* swI = reinterpret_cast<ulonglong2*>(smem + ZP_XS_FLOATS);
    float*      sA  = reinterpret_cast<float*>(swI + 512);
    float*      sB  = sA + 16;

    int tid = threadIdx.x;
    int rg  = tid & 31;
    int kh  = tid >> 5;

    {
        const ulonglong2* srcw = reinterpret_cast<const ulonglong2*>(g_wI);
        for (int i = tid; i < 512; i += 128) swI[i] = srcw[i];
        if (tid < 16) { sA[tid] = g_A[tid]; sB[tid] = g_B[tid]; }
    }

    const float4* src = reinterpret_cast<const float4*>(z) +
                        (size_t)blockIdx.x * 4096;
    #pragma unroll
    for (int it = 0; it < 32; it++) {
        int i = it * 128 + tid;
        float4 v = src[i];
        int r = i >> 5;
        int g = i & 31;
        int col = (r + g) & 127;
        *reinterpret_cast<float4*>(xs + g * 520 + col * 4) = v;
    }
    __syncthreads();

    unsigned long long acc[4][8];
    float s1[4], s2[4];
    #pragma unroll
    for (int c4 = 0; c4 < 4; c4++) {
        s1[c4] = 0.f; s2[c4] = 0.f;
        #pragma unroll
        for (int p = 0; p < 8; p++) acc[c4][p] = 0ULL;
    }

    #pragma unroll 2
    for (int gi = 0; gi < 8; gi++) {
        int g = kh * 8 + gi;
        float xf[4][4];
        #pragma unroll
        for (int c4 = 0; c4 < 4; c4++) {
            int row = rg + 32 * c4;
            int col = (row + g) & 127;
            float4 xv = *reinterpret_cast<const float4*>(xs + g * 520 + col * 4);
            xf[c4][0] = xv.x; xf[c4][1] = xv.y; xf[c4][2] = xv.z; xf[c4][3] = xv.w;
        }
        #pragma unroll
        for (int c = 0; c < 4; c++) {
            const ulonglong2* wr = swI + (4 * g + c) * 4;
            unsigned long long xp[4];
            #pragma unroll
            for (int c4 = 0; c4 < 4; c4++) {
                float x = xf[c4][c];
                s1[c4] += x;
                s2[c4] = fmaf(x, x, s2[c4]);
                xp[c4] = pack2(x, x);
            }
            #pragma unroll
            for (int q = 0; q < 4; q++) {
                ulonglong2 w2 = wr[q];
                #pragma unroll
                for (int c4 = 0; c4 < 4; c4++) {
                    acc[c4][2 * q]     = ffma2(xp[c4], w2.x, acc[c4][2 * q]);
                    acc[c4][2 * q + 1] = ffma2(xp[c4], w2.y, acc[c4][2 * q + 1]);
                }
            }
        }
    }
    __syncthreads();

    if (kh > 0) {
        float* buf = xs + ((kh - 1) * 32 + rg) * 84;
        #pragma unroll
        for (int c4 = 0; c4 < 4; c4++) {
            float t[16];
            #pragma unroll
            for (int p = 0; p < 8; p++) unpack2(acc[c4][p], t[2 * p], t[2 * p + 1]);
            float* bb = buf + c4 * 20;
            #pragma unroll
            for (int j = 0; j < 4; j++)
                *reinterpret_cast<float4*>(bb + 4 * j) =
                    make_float4(t[4 * j], t[4 * j + 1], t[4 * j + 2], t[4 * j + 3]);
            bb[16] = s1[c4];
            bb[17] = s2[c4];
        }
    }
    __syncthreads();

    if (kh == 0) {
        #pragma unroll
        for (int c4 = 0; c4 < 4; c4++) {
            float o[16];
            #pragma unroll
            for (int p = 0; p < 8; p++) unpack2(acc[c4][p], o[2 * p], o[2 * p + 1]);
            float t1 = s1[c4], t2 = s2[c4];
            #pragma unroll
            for (int w = 0; w < 3; w++) {
                const float* bb = xs + (w * 32 + rg) * 84 + c4 * 20;
                #pragma unroll
                for (int j = 0; j < 4; j++) {
                    float4 pv = *reinterpret_cast<const float4*>(bb + 4 * j);
                    o[4 * j + 0] += pv.x; o[4 * j + 1] += pv.y;
                    o[4 * j + 2] += pv.z; o[4 * j + 3] += pv.w;
                }
                t1 += bb[16];
                t2 += bb[17];
            }
            float m    = t1 * (1.f / 128.f);
            float var  = t2 * (1.f / 128.f) - m * m;
            float rstd = rsqrtf(var + 1e-5f);

            size_t row = (size_t)blockIdx.x * 128 + rg + 32 * c4;
            float* dst = g_zp + row * 16;
            #pragma unroll
            for (int j = 0; j < 4; j++) {
                float4 ov;
                ov.x = (o[4*j+0] - m * sA[4*j+0]) * rstd + sB[4*j+0];
                ov.y = (o[4*j+1] - m * sA[4*j+1]) * rstd + sB[4*j+1];
                ov.z = (o[4*j+2] - m * sA[4*j+2]) * rstd + sB[4*j+2];
                ov.w = (o[4*j+3] - m * sA[4*j+3]) * rstd + sB[4*j+3];
                *reinterpret_cast<float4*>(dst + 4 * j) = ov;
            }
        }
    }
}

// ============================================================
// Kernel 4: pairs — 2 queries per block share gathers + weight LDS
// ============================================================
__global__ void __launch_bounds__(128)
pairs_kernel(const float* __restrict__ ref_pos,
             const int*   __restrict__ uid,
             const float* __restrict__ Wp,   // [16,3]
             const float* __restrict__ Wd,   // [16]
             const float* __restrict__ Wm,   // [16]
             const float* __restrict__ W1,
             const float* __restrict__ W2,
             const float* __restrict__ W3,
             float* __restrict__ p_out)
{
    __shared__ __align__(16) float sWi[3][256];
    __shared__ float sWp[64], sWd[16], sWm[16];
    __shared__ float sCq[2][16];
    __shared__ float sPq[2][4];
    __shared__ int   sUq[2];
    int tid = threadIdx.x;
    int nq0 = blockIdx.x * 2;
    int nq1 = nq0 + 1;

    {
        int i = tid;
        #pragma unroll
        for (int it = 0; it < 2; it++, i += 128) {
            int j = i >> 4, op = (i >> 1) & 7, h = i & 1;
            int srcIdx = (2 * op + h) * 16 + j;
            sWi[0][i] = W1[srcIdx];
            sWi[1][i] = W2[srcIdx];
            sWi[2][i] = W3[srcIdx];
        }
    }
    if (tid < 16) {
        sWd[tid] = Wd[tid]; sWm[tid] = Wm[tid];
        sCq[0][tid] = g_cqp[nq0 * 16 + tid];
        sCq[1][tid] = g_cqp[nq1 * 16 + tid];
        sWp[tid * 4 + 0] = Wp[tid * 3 + 0];
        sWp[tid * 4 + 1] = Wp[tid * 3 + 1];
        sWp[tid * 4 + 2] = Wp[tid * 3 + 2];
    }
    if (tid < 2) {
        int nq = nq0 + tid;
        sUq[tid] = uid[nq];
        sPq[tid][0] = ref_pos[nq * 3 + 0];
        sPq[tid][1] = ref_pos[nq * 3 + 1];
        sPq[tid][2] = ref_pos[nq * 3 + 2];
    }
    __syncthreads();

    int khat = nq0 >> 5;
    int nk = 32 * khat - 48 + tid;
    bool valid = (nk >= 0) && (nk < N_ATOMS);

    int uq0 = sUq[0], uq1 = sUq[1];

    float acc0[16], acc1[16];
    #pragma unroll
    for (int zi = 0; zi < 16; zi++) { acc0[zi] = sCq[0][zi]; acc1[zi] = sCq[1][zi]; }

    if (valid) {
        int uk = uid[nk];
        const float4* zr0 = reinterpret_cast<const float4*>(
            g_zp + ((size_t)uq0 * 512 + uk) * 16);
        const float4* cr = reinterpret_cast<const float4*>(g_ckp + nk * 16);
        float zc0[16];
        #pragma unroll
        for (int j = 0; j < 4; j++) {
            float4 zv = zr0[j], cv = cr[j];
            zc0[4*j+0] = zv.x + cv.x; zc0[4*j+1] = zv.y + cv.y;
            zc0[4*j+2] = zv.z + cv.z; zc0[4*j+3] = zv.w + cv.w;
        }
        #pragma unroll
        for (int zi = 0; zi < 16; zi++) acc0[zi] += zc0[zi];
        if (uq1 == uq0) {
            #pragma unroll
            for (int zi = 0; zi < 16; zi++) acc1[zi] += zc0[zi];
        } else {
            const float4* zr1 = reinterpret_cast<const float4*>(
                g_zp + ((size_t)uq1 * 512 + uk) * 16);
            #pragma unroll
            for (int j = 0; j < 4; j++) {
                float4 zv = zr1[j], cv = cr[j];
                acc1[4*j+0] += zv.x + cv.x; acc1[4*j+1] += zv.y + cv.y;
                acc1[4*j+2] += zv.z + cv.z; acc1[4*j+3] += zv.w + cv.w;
            }
        }
        float px = ref_pos[nk * 3 + 0];
        float py = ref_pos[nk * 3 + 1];
        float pz = ref_pos[nk * 3 + 2];
        if (uk == uq0) {
            float dx = px - sPq[0][0], dy = py - sPq[0][1], dz = pz - sPq[0][2];
            float dn = 1.f / (1.f + dx * dx + dy * dy + dz * dz);
            #pragma unroll
            for (int zi = 0; zi < 16; zi++)
                acc0[zi] += sWp[zi*4+0]*dx + sWp[zi*4+1]*dy
                          + sWp[zi*4+2]*dz + sWd[zi]*dn + sWm[zi];
        }
        if (uk == uq1) {
            float dx = px - sPq[1][0], dy = py - sPq[1][1], dz = pz - sPq[1][2];
            float dn = 1.f / (1.f + dx * dx + dy * dy + dz * dz);
            #pragma unroll
            for (int zi = 0; zi < 16; zi++)
                acc1[zi] += sWp[zi*4+0]*dx + sWp[zi*4+1]*dy
                          + sWp[zi*4+2]*dz + sWd[zi]*dn + sWm[zi];
        }
    }

    unsigned long long h0[8], h1[8], g0[8], g1[8];

    #pragma unroll
    for (int p = 0; p < 8; p++) { h0[p] = 0ULL; h1[p] = 0ULL; }
    #pragma unroll
    for (int j = 0; j < 16; j++) {
        float t0 = fmaxf(acc0[j], 0.f), t1 = fmaxf(acc1[j], 0.f);
        unsigned long long xp0 = pack2(t0, t0), xp1 = pack2(t1, t1);
        const ulonglong2* wr = reinterpret_cast<const ulonglong2*>(sWi[0]) + j * 4;
        #pragma unroll
        for (int q = 0; q < 4; q++) {
            ulonglong2 w2 = wr[q];
            h0[2*q]   = ffma2(xp0, w2.x, h0[2*q]);
            h0[2*q+1] = ffma2(xp0, w2.y, h0[2*q+1]);
            h1[2*q]   = ffma2(xp1, w2.x, h1[2*q]);
            h1[2*q+1] = ffma2(xp1, w2.y, h1[2*q+1]);
        }
    }
    #pragma unroll
    for (int p = 0; p < 8; p++) { g0[p] = 0ULL; g1[p] = 0ULL; }
    #pragma unroll
    for (int p = 0; p < 8; p++) {
        float a0, a1, b0, b1;
        unpack2(h0[p], a0, a1); unpack2(h1[p], b0, b1);
        a0 = fmaxf(a0, 0.f); a1 = fmaxf(a1, 0.f);
        b0 = fmaxf(b0, 0.f); b1 = fmaxf(b1, 0.f);
        unsigned long long xa0 = pack2(a0, a0), xa1 = pack2(a1, a1);
        unsigned long long xb0 = pack2(b0, b0), xb1 = pack2(b1, b1);
        const ulonglong2* wr0 = reinterpret_cast<const ulonglong2*>(sWi[1]) + (2*p) * 4;
        const ulonglong2* wr1 = wr0 + 4;
        #pragma unroll
        for (int q = 0; q < 4; q++) {
            ulonglong2 wA = wr0[q];
            g0[2*q]   = ffma2(xa0, wA.x, g0[2*q]);
            g0[2*q+1] = ffma2(xa0, wA.y, g0[2*q+1]);
            g1[2*q]   = ffma2(xb0, wA.x, g1[2*q]);
            g1[2*q+1] = ffma2(xb0, wA.y, g1[2*q+1]);
            ulonglong2 wB = wr1[q];
            g0[2*q]   = ffma2(xa1, wB.x, g0[2*q]);
            g0[2*q+1] = ffma2(xa1, wB.y, g0[2*q+1]);
            g1[2*q]   = ffma2(xb1, wB.x, g1[2*q]);
            g1[2*q+1] = ffma2(xb1, wB.y, g1[2*q+1]);
        }
    }
    #pragma unroll
    for (int p = 0; p < 8; p++) { h0[p] = 0ULL; h1[p] = 0ULL; }
    #pragma unroll
    for (int p = 0; p < 8; p++) {
        float a0, a1, b0, b1;
        unpack2(g0[p], a0, a1); unpack2(g1[p], b0, b1);
        a0 = fmaxf(a0, 0.f); a1 = fmaxf(a1, 0.f);
        b0 = fmaxf(b0, 0.f); b1 = fmaxf(b1, 0.f);
        unsigned long long xa0 = pack2(a0, a0), xa1 = pack2(a1, a1);
        unsigned long long xb0 = pack2(b0, b0), xb1 = pack2(b1, b1);
        const ulonglong2* wr0 = reinterpret_cast<const ulonglong2*>(sWi[2]) + (2*p) * 4;
        const ulonglong2* wr1 = wr0 + 4;
        #pragma unroll
        for (int q = 0; q < 4; q++) {
            ulonglong2 wA = wr0[q];
            h0[2*q]   = ffma2(xa0, wA.x, h0[2*q]);
            h0[2*q+1] = ffma2(xa0, wA.y, h0[2*q+1]);
            h1[2*q]   = ffma2(xb0, wA.x, h1[2*q]);
            h1[2*q+1] = ffma2(xb0, wA.y, h1[2*q+1]);
            ulonglong2 wB = wr1[q];
            h0[2*q]   = ffma2(xa1, wB.x, h0[2*q]);
            h0[2*q+1] = ffma2(xa1, wB.y, h0[2*q+1]);
            h1[2*q]   = ffma2(xb1, wB.x, h1[2*q]);
            h1[2*q+1] = ffma2(xb1, wB.y, h1[2*q+1]);
        }
    }
    #pragma unroll
    for (int p = 0; p < 8; p++) {
        float lo, hi;
        unpack2(h0[p], lo, hi);
        acc0[2*p] += lo; acc0[2*p+1] += hi;
        unpack2(h1[p], lo, hi);
        acc1[2*p] += lo; acc1[2*p+1] += hi;
    }

    float* dst0 = p_out + ((size_t)nq0 * 128 + tid) * 16;
    float* dst1 = p_out + ((size_t)nq1 * 128 + tid) * 16;
    #pragma unroll
    for (int j = 0; j < 4; j++) {
        *reinterpret_cast<float4*>(dst0 + 4*j) =
            make_float4(acc0[4*j], acc0[4*j+1], acc0[4*j+2], acc0[4*j+3]);
        *reinterpret_cast<float4*>(dst1 + 4*j) =
            make_float4(acc1[4*j], acc1[4*j+1], acc1[4*j+2], acc1[4*j+3]);
    }
}

// ============================================================
extern "C" void kernel_launch(void* const* d_in, const int* in_sizes, int n_in,
                              void* d_out, int out_size)
{
    const float* ref_pos     = (const float*)d_in[0];
    const float* ref_charge  = (const float*)d_in[1];
    const float* ref_element = (const float*)d_in[2];
    const float* ref_chars   = (const float*)d_in[3];
    const float* s_trunk     = (const float*)d_in[5];
    const float* z           = (const float*)d_in[6];
    const float* W_feat      = (const float*)d_in[7];
    const float* b_feat      = (const float*)d_in[8];
    const float* W_rp        = (const float*)d_in[9];
    const float* W_rd        = (const float*)d_in[10];
    const float* W_msk       = (const float*)d_in[11];
    const float* ln_s_s      = (const float*)d_in[12];
    const float* ln_s_b      = (const float*)d_in[13];
    const float* W_s2c       = (const float*)d_in[14];
    const float* ln_z_s      = (const float*)d_in[15];
    const float* ln_z_b      = (const float*)d_in[16];
    const float* W_z2p       = (const float*)d_in[17];
    const float* W_cq        = (const float*)d_in[18];
    const float* W_ck        = (const float*)d_in[19];
    const float* W1          = (const float*)d_in[20];
    const float* W2          = (const float*)d_in[21];
    const float* W3          = (const float*)d_in[22];
    const int*   uid         = (const int*)d_in[24];

    float* out   = (float*)d_out;
    float* q_out = out;
    float* c_out = out + (size_t)N_ATOMS * AS;
    float* p_out = out + (size_t)2 * N_ATOMS * AS;

    static cudaStream_t s_side = nullptr;
    static cudaEvent_t  e_fork = nullptr, e_join = nullptr;
    static bool s_init = false;
    if (!s_init) {
        s_init = true;
        if (cudaStreamCreateWithFlags(&s_side, cudaStreamNonBlocking) != cudaSuccess)
            s_side = nullptr;
        if (s_side) {
            if (cudaEventCreateWithFlags(&e_fork, cudaEventDisableTiming) != cudaSuccess ||
                cudaEventCreateWithFlags(&e_join, cudaEventDisableTiming) != cudaSuccess) {
                s_side = nullptr;
            }
        }
    }
    cudaFuncSetAttribute(zp_kernel,
                         cudaFuncAttributeMaxDynamicSharedMemorySize, ZP_SMEM);

    bool overlap = (s_side != nullptr);
    cudaStream_t sc = overlap ? s_side : (cudaStream_t)0;

    if (overlap) {
        cudaEventRecord(e_fork, 0);
        cudaStreamWaitEvent(sc, e_fork, 0);
    }

    // R10 launch order: prep + zp on s0 first, s2c + c on side stream
    prep_kernel<<<1, 128>>>(ln_z_s, ln_z_b, W_z2p);                          // #1 s0
    zp_kernel  <<<T_TOK * T_TOK / 128, 128, ZP_SMEM>>>(z);                   // #2 s0
    s2c_kernel <<<T_TOK / 4, 128, 0, sc>>>(s_trunk, ln_s_s, ln_s_b, W_s2c);  // #3 side
    c_kernel   <<<N_ATOMS / 16, 128, 0, sc>>>(ref_pos, ref_charge, ref_element,
                                              ref_chars, W_feat, b_feat,
                                              W_cq, W_ck, uid, q_out, c_out); // #4 side
    if (overlap) {
        cudaEventRecord(e_join, sc);
        cudaStreamWaitEvent(0, e_join, 0);
    }
    pairs_kernel<<<N_ATOMS / 2, 128>>>(ref_pos, uid, W_rp, W_rd, W_msk,
                                       W1, W2, W3, p_out);                    // #5 s0
    (void)in_sizes; (void)n_in; (void)out_size;
}

// round 17
// speedup vs baseline: 1.5591x; 1.0448x over previous
#include <cuda_runtime.h>

// ---------------- problem constants ----------------
constexpr int N_ATOMS = 4096;
constexpr int T_TOK   = 512;
constexpr int AS      = 128;   // atom_s
constexpr int AZ      = 16;    // atom_z
constexpr int TS      = 384;   // token_s
constexpr int FD      = 388;   // feat_dim

// ---------------- scratch (device globals; no allocation) ----------------
__device__ float g_s2c[T_TOK * AS];
__device__ float g_zp [T_TOK * T_TOK * AZ];            // 16.8 MB
__device__ float g_cqp[N_ATOMS * AZ];
__device__ float g_ckp[N_ATOMS * AZ];
__device__ unsigned long long g_wI[128 * 8];           // zp weights, z-pair interleaved
__device__ float g_A[16];
__device__ float g_B[16];

// ---------------- f32x2 helpers ----------------
__device__ __forceinline__ unsigned long long ffma2(unsigned long long a,
                                                    unsigned long long b,
                                                    unsigned long long c)
{
    unsigned long long d;
    asm("fma.rn.f32x2 %0, %1, %2, %3;" : "=l"(d) : "l"(a), "l"(b), "l"(c));
    return d;
}
__device__ __forceinline__ unsigned long long pack2(float lo, float hi)
{
    unsigned long long d;
    asm("mov.b64 %0, {%1, %2};" : "=l"(d) : "f"(lo), "f"(hi));
    return d;
}
__device__ __forceinline__ void unpack2(unsigned long long v, float& lo, float& hi)
{
    asm("mov.b64 {%0, %1}, %2;" : "=f"(lo), "=f"(hi) : "l"(v));
}

// ============================================================
// Kernel 0 (v1): prep — fold LN scale into W_z_to_p, pair-interleave
// ============================================================
__global__ void prep_kernel(const float* __restrict__ ln_scale,
                            const float* __restrict__ ln_bias,
                            const float* __restrict__ Wz)   // [16,128]
{
    int tid = threadIdx.x;
    float* wf = reinterpret_cast<float*>(g_wI);
    for (int i = tid; i < 2048; i += 128) {
        int k = i >> 4, p = (i >> 1) & 7, h = i & 1;
        wf[i] = ln_scale[k] * Wz[(2 * p + h) * 128 + k];
    }
    if (tid < 16) {
        float a = 0.f, b = 0.f;
        for (int l = 0; l < 128; l++) {
            float w = Wz[tid * 128 + l];
            a += ln_scale[l] * w;
            b += ln_bias[l] * w;
        }
        g_A[tid] = a;
        g_B[tid] = b;
    }
}

// ============================================================
// Kernel 1 (v1): s2c[t][j] = LN(s_trunk[t]) @ W_s_to_c^T  (4 tokens/block)
// ============================================================
__global__ void s2c_kernel(const float* __restrict__ s_trunk,
                           const float* __restrict__ ln_scale,
                           const float* __restrict__ ln_bias,
                           const float* __restrict__ W)   // [128,384]
{
    __shared__ float xn[4 * 388];
    __shared__ float wc[32 * 132];
    int tid = threadIdx.x;
    int t0  = blockIdx.x * 4;

    for (int i = tid; i < 4 * TS; i += 128) {
        int r = i / TS, k = i - r * TS;
        xn[r * 388 + k] = s_trunk[(t0 + r) * TS + k];
    }
    __syncthreads();

    int r = tid >> 5, s = tid & 31;
    float s1 = 0.f, s2 = 0.f;
    for (int k = s * 12; k < s * 12 + 12; k++) {
        float x = xn[r * 388 + k]; s1 += x; s2 += x * x;
    }
    #pragma unroll
    for (int o = 16; o >= 1; o >>= 1) {
        s1 += __shfl_xor_sync(~0u, s1, o);
        s2 += __shfl_xor_sync(~0u, s2, o);
    }
    float m    = s1 * (1.f / TS);
    float var  = s2 * (1.f / TS) - m * m;
    float rstd = rsqrtf(var + 1e-5f);
    for (int k = s * 12; k < s * 12 + 12; k++) {
        float x = xn[r * 388 + k];
        xn[r * 388 + k] = (x - m) * rstd * ln_scale[k] + ln_bias[k];
    }
    __syncthreads();

    float acc[4] = {0.f, 0.f, 0.f, 0.f};
    for (int k0 = 0; k0 < TS; k0 += 32) {
        const float4* wr = reinterpret_cast<const float4*>(W + tid * TS + k0);
        #pragma unroll
        for (int q = 0; q < 8; q++) {
            float4 w4 = wr[q];
            wc[(q * 4 + 0) * 132 + tid] = w4.x;
            wc[(q * 4 + 1) * 132 + tid] = w4.y;
            wc[(q * 4 + 2) * 132 + tid] = w4.z;
            wc[(q * 4 + 3) * 132 + tid] = w4.w;
        }
        __syncthreads();
        #pragma unroll
        for (int kk = 0; kk < 32; kk += 4) {
            float w0 = wc[(kk + 0) * 132 + tid];
            float w1 = wc[(kk + 1) * 132 + tid];
            float w2 = wc[(kk + 2) * 132 + tid];
            float w3 = wc[(kk + 3) * 132 + tid];
            #pragma unroll
            for (int a = 0; a < 4; a++) {
                float4 x4 = *reinterpret_cast<const float4*>(&xn[a * 388 + k0 + kk]);
                acc[a] += x4.x * w0 + x4.y * w1 + x4.z * w2 + x4.w * w3;
            }
        }
        __syncthreads();
    }
    #pragma unroll
    for (int a = 0; a < 4; a++)
        g_s2c[(t0 + a) * AS + tid] = acc[a];
}

// ============================================================
// Kernel 2 (v7): c = feats @ W^T + b — v3 mainloop with 2-way K-SPLIT.
//   256 threads: ch = tid&127 (output channel), kh = tid>>7 (k half).
//   kh=0: k 0..191 (12 chunks); kh=1: k 192..387 (12 chunks + 4 tail).
//   Halves combined via smem comb (stride 17, conflict-free).
// ============================================================
__global__ void __launch_bounds__(256)
c_kernel(const float* __restrict__ ref_pos,
         const float* __restrict__ ref_charge,
         const float* __restrict__ ref_element,
         const float* __restrict__ ref_chars,
         const float* __restrict__ W_feat,  // [128,388]
         const float* __restrict__ b_feat,
         const float* __restrict__ Wq16,    // [16,128]
         const float* __restrict__ Wk16,    // [16,128]
         const int*   __restrict__ uid,
         float* __restrict__ q_out,
         float* __restrict__ c_out)
{
    // region map:
    //   mainloop: faI features [0 .. 7760)            (388 rows x 20)
    //   post:     comb [0 .. 2176)  (128ch x 17)
    //             cs   [2304 .. 4416)  (16 x 132)
    //             wqk  [4416 .. 8640)  (32 x 132)
    __shared__ __align__(16) float faI[8704];
    int tid = threadIdx.x;
    int n0  = blockIdx.x * 16;
    int ch  = tid & 127;
    int kh  = tid >> 7;

    // stage transposed features (256 threads)
    for (int i = tid; i < 16 * 128; i += 256) {
        int a = i >> 7, e = i & 127;
        faI[(4 + e) * 20 + a] = ref_element[(n0 + a) * 128 + e];
    }
    for (int i = tid; i < 16 * 256; i += 256) {
        int a = i >> 8, e = i & 255;
        faI[(132 + e) * 20 + a] = ref_chars[(n0 + a) * 256 + e];
    }
    if (tid < 64) {
        int a = tid >> 2, cm = tid & 3;
        faI[cm * 20 + a] = (cm < 3) ? ref_pos[(n0 + a) * 3 + cm]
                                    : ref_charge[n0 + a];
    }

    const float* wrow = W_feat + ch * FD + kh * 192;
    float4 cw0 = *reinterpret_cast<const float4*>(wrow + 0);
    float4 cw1 = *reinterpret_cast<const float4*>(wrow + 4);
    float4 cw2 = *reinterpret_cast<const float4*>(wrow + 8);
    float4 cw3 = *reinterpret_cast<const float4*>(wrow + 12);

    unsigned long long accp[8];
    {
        float bj = (kh == 0) ? b_feat[ch] : 0.f;
        unsigned long long bb = pack2(bj, bj);
        #pragma unroll
        for (int p = 0; p < 8; p++) accp[p] = bb;
    }
    __syncthreads();   // features staged

    for (int cI = 0; cI < 12; cI++) {
        float wv[16] = {cw0.x, cw0.y, cw0.z, cw0.w,
                        cw1.x, cw1.y, cw1.z, cw1.w,
                        cw2.x, cw2.y, cw2.z, cw2.w,
                        cw3.x, cw3.y, cw3.z, cw3.w};
        if (cI < 11) {
            const float* nb = wrow + (cI + 1) * 16;
            cw0 = *reinterpret_cast<const float4*>(nb + 0);
            cw1 = *reinterpret_cast<const float4*>(nb + 4);
            cw2 = *reinterpret_cast<const float4*>(nb + 8);
            cw3 = *reinterpret_cast<const float4*>(nb + 12);
        }
        int kbase = kh * 192 + cI * 16;
        #pragma unroll
        for (int kk = 0; kk < 16; kk++) {
            unsigned long long wp = pack2(wv[kk], wv[kk]);
            const ulonglong2* xr =
                reinterpret_cast<const ulonglong2*>(faI + (kbase + kk) * 20);
            #pragma unroll
            for (int p = 0; p < 4; p++) {
                ulonglong2 x2 = xr[p];
                accp[2 * p]     = ffma2(x2.x, wp, accp[2 * p]);
                accp[2 * p + 1] = ffma2(x2.y, wp, accp[2 * p + 1]);
            }
        }
    }
    if (kh == 1) {   // tail k = 384..387
        float4 wt = *reinterpret_cast<const float4*>(W_feat + ch * FD + 384);
        float wv[4] = {wt.x, wt.y, wt.z, wt.w};
        #pragma unroll
        for (int j = 0; j < 4; j++) {
            unsigned long long wp = pack2(wv[j], wv[j]);
            const ulonglong2* xr =
                reinterpret_cast<const ulonglong2*>(faI + (384 + j) * 20);
            #pragma unroll
            for (int p = 0; p < 4; p++) {
                ulonglong2 x2 = xr[p];
                accp[2 * p]     = ffma2(x2.x, wp, accp[2 * p]);
                accp[2 * p + 1] = ffma2(x2.y, wp, accp[2 * p + 1]);
            }
        }
    }
    __syncthreads();   // ALL mainloop reads of faI done

    // phase 1: kh=1 writes partials to comb; all threads stage Wq/Wk
    float* comb = faI;           // [0 .. 2176)
    float* cs   = faI + 2304;    // 16 x 132
    float* wqk  = faI + 4416;    // 32 x 132
    if (kh == 1) {
        float t[16];
        #pragma unroll
        for (int p = 0; p < 8; p++) unpack2(accp[p], t[2 * p], t[2 * p + 1]);
        #pragma unroll
        for (int a = 0; a < 16; a++) comb[ch * 17 + a] = t[a];
    }
    for (int i = tid; i < 32 * 128; i += 256) {
        int rr = i >> 7, l = i & 127;
        wqk[rr * 132 + l] = (rr < 16) ? Wq16[rr * 128 + l]
                                      : Wk16[(rr - 16) * 128 + l];
    }
    __syncthreads();

    // phase 2: kh=0 combines, writes q/c and cs
    if (kh == 0) {
        float cval[16];
        #pragma unroll
        for (int p = 0; p < 8; p++)
            unpack2(accp[p], cval[2 * p], cval[2 * p + 1]);
        #pragma unroll
        for (int a = 0; a < 16; a++) {
            int n = n0 + a;
            float v = cval[a] + comb[ch * 17 + a];
            q_out[n * AS + ch] = v;
            v += g_s2c[uid[n] * AS + ch];
            c_out[n * AS + ch] = v;
            cs[a * 132 + ch] = v;
        }
    }
    __syncthreads();

    // phase 3: epilogue — 256 threads, one atom + 2 outputs each
    int a  = tid >> 4, oo = tid & 15;
    float o0 = 0.f, o1 = 0.f;
    #pragma unroll 4
    for (int l = 0; l < 128; l++) {
        float x = fmaxf(cs[a * 132 + l], 0.f);
        o0 = fmaf(x, wqk[oo * 132 + l], o0);
        o1 = fmaf(x, wqk[(oo + 16) * 132 + l], o1);
    }
    int n = n0 + a;
    g_cqp[n * 16 + oo] = o0;
    g_ckp[n * 16 + oo] = o1;
}

// ============================================================
// Kernel 3 (v5, measured 50.9us): zp — 128 rows/block,
//   4 rows/thread, 4-way k-split with warp == k-split.
// ============================================================
constexpr int ZP_XS_FLOATS = 16640;
constexpr int ZP_SMEM = ZP_XS_FLOATS * 4 + 512 * 16 + 2 * 16 * 4;  // ~74.8 KB

__global__ void __launch_bounds__(128)
zp_kernel(const float* __restrict__ z)
{
    extern __shared__ __align__(16) float smem[];
    float*      xs  = smem;
    ulonglong2* swI = reinterpret_cast<ulonglong2*>(smem + ZP_XS_FLOATS);
    float*      sA  = reinterpret_cast<float*>(swI + 512);
    float*      sB  = sA + 16;

    int tid = threadIdx.x;
    int rg  = tid & 31;
    int kh  = tid >> 5;

    {
        const ulonglong2* srcw = reinterpret_cast<const ulonglong2*>(g_wI);
        for (int i = tid; i < 512; i += 128) swI[i] = srcw[i];
        if (tid < 16) { sA[tid] = g_A[tid]; sB[tid] = g_B[tid]; }
    }

    const float4* src = reinterpret_cast<const float4*>(z) +
                        (size_t)blockIdx.x * 4096;
    #pragma unroll
    for (int it = 0; it < 32; it++) {
        int i = it * 128 + tid;
        float4 v = src[i];
        int r = i >> 5;
        int g = i & 31;
        int col = (r + g) & 127;
        *reinterpret_cast<float4*>(xs + g * 520 + col * 4) = v;
    }
    __syncthreads();

    unsigned long long acc[4][8];
    float s1[4], s2[4];
    #pragma unroll
    for (int c4 = 0; c4 < 4; c4++) {
        s1[c4] = 0.f; s2[c4] = 0.f;
        #pragma unroll
        for (int p = 0; p < 8; p++) acc[c4][p] = 0ULL;
    }

    #pragma unroll 2
    for (int gi = 0; gi < 8; gi++) {
        int g = kh * 8 + gi;
        float xf[4][4];
        #pragma unroll
        for (int c4 = 0; c4 < 4; c4++) {
            int row = rg + 32 * c4;
            int col = (row + g) & 127;
            float4 xv = *reinterpret_cast<const float4*>(xs + g * 520 + col * 4);
            xf[c4][0] = xv.x; xf[c4][1] = xv.y; xf[c4][2] = xv.z; xf[c4][3] = xv.w;
        }
        #pragma unroll
        for (int c = 0; c < 4; c++) {
            const ulonglong2* wr = swI + (4 * g + c) * 4;
            unsigned long long xp[4];
            #pragma unroll
            for (int c4 = 0; c4 < 4; c4++) {
                float x = xf[c4][c];
                s1[c4] += x;
                s2[c4] = fmaf(x, x, s2[c4]);
                xp[c4] = pack2(x, x);
            }
            #pragma unroll
            for (int q = 0; q < 4; q++) {
                ulonglong2 w2 = wr[q];
                #pragma unroll
                for (int c4 = 0; c4 < 4; c4++) {
                    acc[c4][2 * q]     = ffma2(xp[c4], w2.x, acc[c4][2 * q]);
                    acc[c4][2 * q + 1] = ffma2(xp[c4], w2.y, acc[c4][2 * q + 1]);
                }
            }
        }
    }
    __syncthreads();

    if (kh > 0) {
        float* buf = xs + ((kh - 1) * 32 + rg) * 84;
        #pragma unroll
        for (int c4 = 0; c4 < 4; c4++) {
            float t[16];
            #pragma unroll
            for (int p = 0; p < 8; p++) unpack2(acc[c4][p], t[2 * p], t[2 * p + 1]);
            float* bb = buf + c4 * 20;
            #pragma unroll
            for (int j = 0; j < 4; j++)
                *reinterpret_cast<float4*>(bb + 4 * j) =
                    make_float4(t[4 * j], t[4 * j + 1], t[4 * j + 2], t[4 * j + 3]);
            bb[16] = s1[c4];
            bb[17] = s2[c4];
        }
    }
    __syncthreads();

    if (kh == 0) {
        #pragma unroll
        for (int c4 = 0; c4 < 4; c4++) {
            float o[16];
            #pragma unroll
            for (int p = 0; p < 8; p++) unpack2(acc[c4][p], o[2 * p], o[2 * p + 1]);
            float t1 = s1[c4], t2 = s2[c4];
            #pragma unroll
            for (int w = 0; w < 3; w++) {
                const float* bb = xs + (w * 32 + rg) * 84 + c4 * 20;
                #pragma unroll
                for (int j = 0; j < 4; j++) {
                    float4 pv = *reinterpret_cast<const float4*>(bb + 4 * j);
                    o[4 * j + 0] += pv.x; o[4 * j + 1] += pv.y;
                    o[4 * j + 2] += pv.z; o[4 * j + 3] += pv.w;
                }
                t1 += bb[16];
                t2 += bb[17];
            }
            float m    = t1 * (1.f / 128.f);
            float var  = t2 * (1.f / 128.f) - m * m;
            float rstd = rsqrtf(var + 1e-5f);

            size_t row = (size_t)blockIdx.x * 128 + rg + 32 * c4;
            float* dst = g_zp + row * 16;
            #pragma unroll
            for (int j = 0; j < 4; j++) {
                float4 ov;
                ov.x = (o[4*j+0] - m * sA[4*j+0]) * rstd + sB[4*j+0];
                ov.y = (o[4*j+1] - m * sA[4*j+1]) * rstd + sB[4*j+1];
                ov.z = (o[4*j+2] - m * sA[4*j+2]) * rstd + sB[4*j+2];
                ov.w = (o[4*j+3] - m * sA[4*j+3]) * rstd + sB[4*j+3];
                *reinterpret_cast<float4*>(dst + 4 * j) = ov;
            }
        }
    }
}

// ============================================================
// Kernel 4: pairs — 2 queries per block share gathers + weight LDS
// ============================================================
__global__ void __launch_bounds__(128)
pairs_kernel(const float* __restrict__ ref_pos,
             const int*   __restrict__ uid,
             const float* __restrict__ Wp,   // [16,3]
             const float* __restrict__ Wd,   // [16]
             const float* __restrict__ Wm,   // [16]
             const float* __restrict__ W1,
             const float* __restrict__ W2,
             const float* __restrict__ W3,
             float* __restrict__ p_out)
{
    __shared__ __align__(16) float sWi[3][256];
    __shared__ float sWp[64], sWd[16], sWm[16];
    __shared__ float sCq[2][16];
    __shared__ float sPq[2][4];
    __shared__ int   sUq[2];
    int tid = threadIdx.x;
    int nq0 = blockIdx.x * 2;
    int nq1 = nq0 + 1;

    {
        int i = tid;
        #pragma unroll
        for (int it = 0; it < 2; it++, i += 128) {
            int j = i >> 4, op = (i >> 1) & 7, h = i & 1;
            int srcIdx = (2 * op + h) * 16 + j;
            sWi[0][i] = W1[srcIdx];
            sWi[1][i] = W2[srcIdx];
            sWi[2][i] = W3[srcIdx];
        }
    }
    if (tid < 16) {
        sWd[tid] = Wd[tid]; sWm[tid] = Wm[tid];
        sCq[0][tid] = g_cqp[nq0 * 16 + tid];
        sCq[1][tid] = g_cqp[nq1 * 16 + tid];
        sWp[tid * 4 + 0] = Wp[tid * 3 + 0];
        sWp[tid * 4 + 1] = Wp[tid * 3 + 1];
        sWp[tid * 4 + 2] = Wp[tid * 3 + 2];
    }
    if (tid < 2) {
        int nq = nq0 + tid;
        sUq[tid] = uid[nq];
        sPq[tid][0] = ref_pos[nq * 3 + 0];
        sPq[tid][1] = ref_pos[nq * 3 + 1];
        sPq[tid][2] = ref_pos[nq * 3 + 2];
    }
    __syncthreads();

    int khat = nq0 >> 5;
    int nk = 32 * khat - 48 + tid;
    bool valid = (nk >= 0) && (nk < N_ATOMS);

    int uq0 = sUq[0], uq1 = sUq[1];

    float acc0[16], acc1[16];
    #pragma unroll
    for (int zi = 0; zi < 16; zi++) { acc0[zi] = sCq[0][zi]; acc1[zi] = sCq[1][zi]; }

    if (valid) {
        int uk = uid[nk];
        const float4* zr0 = reinterpret_cast<const float4*>(
            g_zp + ((size_t)uq0 * 512 + uk) * 16);
        const float4* cr = reinterpret_cast<const float4*>(g_ckp + nk * 16);
        float zc0[16];
        #pragma unroll
        for (int j = 0; j < 4; j++) {
            float4 zv = zr0[j], cv = cr[j];
            zc0[4*j+0] = zv.x + cv.x; zc0[4*j+1] = zv.y + cv.y;
            zc0[4*j+2] = zv.z + cv.z; zc0[4*j+3] = zv.w + cv.w;
        }
        #pragma unroll
        for (int zi = 0; zi < 16; zi++) acc0[zi] += zc0[zi];
        if (uq1 == uq0) {
            #pragma unroll
            for (int zi = 0; zi < 16; zi++) acc1[zi] += zc0[zi];
        } else {
            const float4* zr1 = reinterpret_cast<const float4*>(
                g_zp + ((size_t)uq1 * 512 + uk) * 16);
            #pragma unroll
            for (int j = 0; j < 4; j++) {
                float4 zv = zr1[j], cv = cr[j];
                acc1[4*j+0] += zv.x + cv.x; acc1[4*j+1] += zv.y + cv.y;
                acc1[4*j+2] += zv.z + cv.z; acc1[4*j+3] += zv.w + cv.w;
            }
        }
        float px = ref_pos[nk * 3 + 0];
        float py = ref_pos[nk * 3 + 1];
        float pz = ref_pos[nk * 3 + 2];
        if (uk == uq0) {
            float dx = px - sPq[0][0], dy = py - sPq[0][1], dz = pz - sPq[0][2];
            float dn = 1.f / (1.f + dx * dx + dy * dy + dz * dz);
            #pragma unroll
            for (int zi = 0; zi < 16; zi++)
                acc0[zi] += sWp[zi*4+0]*dx + sWp[zi*4+1]*dy
                          + sWp[zi*4+2]*dz + sWd[zi]*dn + sWm[zi];
        }
        if (uk == uq1) {
            float dx = px - sPq[1][0], dy = py - sPq[1][1], dz = pz - sPq[1][2];
            float dn = 1.f / (1.f + dx * dx + dy * dy + dz * dz);
            #pragma unroll
            for (int zi = 0; zi < 16; zi++)
                acc1[zi] += sWp[zi*4+0]*dx + sWp[zi*4+1]*dy
                          + sWp[zi*4+2]*dz + sWd[zi]*dn + sWm[zi];
        }
    }

    unsigned long long h0[8], h1[8], g0[8], g1[8];

    #pragma unroll
    for (int p = 0; p < 8; p++) { h0[p] = 0ULL; h1[p] = 0ULL; }
    #pragma unroll
    for (int j = 0; j < 16; j++) {
        float t0 = fmaxf(acc0[j], 0.f), t1 = fmaxf(acc1[j], 0.f);
        unsigned long long xp0 = pack2(t0, t0), xp1 = pack2(t1, t1);
        const ulonglong2* wr = reinterpret_cast<const ulonglong2*>(sWi[0]) + j * 4;
        #pragma unroll
        for (int q = 0; q < 4; q++) {
            ulonglong2 w2 = wr[q];
            h0[2*q]   = ffma2(xp0, w2.x, h0[2*q]);
            h0[2*q+1] = ffma2(xp0, w2.y, h0[2*q+1]);
            h1[2*q]   = ffma2(xp1, w2.x, h1[2*q]);
            h1[2*q+1] = ffma2(xp1, w2.y, h1[2*q+1]);
        }
    }
    #pragma unroll
    for (int p = 0; p < 8; p++) { g0[p] = 0ULL; g1[p] = 0ULL; }
    #pragma unroll
    for (int p = 0; p < 8; p++) {
        float a0, a1, b0, b1;
        unpack2(h0[p], a0, a1); unpack2(h1[p], b0, b1);
        a0 = fmaxf(a0, 0.f); a1 = fmaxf(a1, 0.f);
        b0 = fmaxf(b0, 0.f); b1 = fmaxf(b1, 0.f);
        unsigned long long xa0 = pack2(a0, a0), xa1 = pack2(a1, a1);
        unsigned long long xb0 = pack2(b0, b0), xb1 = pack2(b1, b1);
        const ulonglong2* wr0 = reinterpret_cast<const ulonglong2*>(sWi[1]) + (2*p) * 4;
        const ulonglong2* wr1 = wr0 + 4;
        #pragma unroll
        for (int q = 0; q < 4; q++) {
            ulonglong2 wA = wr0[q];
            g0[2*q]   = ffma2(xa0, wA.x, g0[2*q]);
            g0[2*q+1] = ffma2(xa0, wA.y, g0[2*q+1]);
            g1[2*q]   = ffma2(xb0, wA.x, g1[2*q]);
            g1[2*q+1] = ffma2(xb0, wA.y, g1[2*q+1]);
            ulonglong2 wB = wr1[q];
            g0[2*q]   = ffma2(xa1, wB.x, g0[2*q]);
            g0[2*q+1] = ffma2(xa1, wB.y, g0[2*q+1]);
            g1[2*q]   = ffma2(xb1, wB.x, g1[2*q]);
            g1[2*q+1] = ffma2(xb1, wB.y, g1[2*q+1]);
        }
    }
    #pragma unroll
    for (int p = 0; p < 8; p++) { h0[p] = 0ULL; h1[p] = 0ULL; }
    #pragma unroll
    for (int p = 0; p < 8; p++) {
        float a0, a1, b0, b1;
        unpack2(g0[p], a0, a1); unpack2(g1[p], b0, b1);
        a0 = fmaxf(a0, 0.f); a1 = fmaxf(a1, 0.f);
        b0 = fmaxf(b0, 0.f); b1 = fmaxf(b1, 0.f);
        unsigned long long xa0 = pack2(a0, a0), xa1 = pack2(a1, a1);
        unsigned long long xb0 = pack2(b0, b0), xb1 = pack2(b1, b1);
        const ulonglong2* wr0 = reinterpret_cast<const ulonglong2*>(sWi[2]) + (2*p) * 4;
        const ulonglong2* wr1 = wr0 + 4;
        #pragma unroll
        for (int q = 0; q < 4; q++) {
            ulonglong2 wA = wr0[q];
            h0[2*q]   = ffma2(xa0, wA.x, h0[2*q]);
            h0[2*q+1] = ffma2(xa0, wA.y, h0[2*q+1]);
            h1[2*q]   = ffma2(xb0, wA.x, h1[2*q]);
            h1[2*q+1] = ffma2(xb0, wA.y, h1[2*q+1]);
            ulonglong2 wB = wr1[q];
            h0[2*q]   = ffma2(xa1, wB.x, h0[2*q]);
            h0[2*q+1] = ffma2(xa1, wB.y, h0[2*q+1]);
            h1[2*q]   = ffma2(xb1, wB.x, h1[2*q]);
            h1[2*q+1] = ffma2(xb1, wB.y, h1[2*q+1]);
        }
    }
    #pragma unroll
    for (int p = 0; p < 8; p++) {
        float lo, hi;
        unpack2(h0[p], lo, hi);
        acc0[2*p] += lo; acc0[2*p+1] += hi;
        unpack2(h1[p], lo, hi);
        acc1[2*p] += lo; acc1[2*p+1] += hi;
    }

    float* dst0 = p_out + ((size_t)nq0 * 128 + tid) * 16;
    float* dst1 = p_out + ((size_t)nq1 * 128 + tid) * 16;
    #pragma unroll
    for (int j = 0; j < 4; j++) {
        *reinterpret_cast<float4*>(dst0 + 4*j) =
            make_float4(acc0[4*j], acc0[4*j+1], acc0[4*j+2], acc0[4*j+3]);
        *reinterpret_cast<float4*>(dst1 + 4*j) =
            make_float4(acc1[4*j], acc1[4*j+1], acc1[4*j+2], acc1[4*j+3]);
    }
}

// ============================================================
extern "C" void kernel_launch(void* const* d_in, const int* in_sizes, int n_in,
                              void* d_out, int out_size)
{
    const float* ref_pos     = (const float*)d_in[0];
    const float* ref_charge  = (const float*)d_in[1];
    const float* ref_element = (const float*)d_in[2];
    const float* ref_chars   = (const float*)d_in[3];
    const float* s_trunk     = (const float*)d_in[5];
    const float* z           = (const float*)d_in[6];
    const float* W_feat      = (const float*)d_in[7];
    const float* b_feat      = (const float*)d_in[8];
    const float* W_rp        = (const float*)d_in[9];
    const float* W_rd        = (const float*)d_in[10];
    const float* W_msk       = (const float*)d_in[11];
    const float* ln_s_s      = (const float*)d_in[12];
    const float* ln_s_b      = (const float*)d_in[13];
    const float* W_s2c       = (const float*)d_in[14];
    const float* ln_z_s      = (const float*)d_in[15];
    const float* ln_z_b      = (const float*)d_in[16];
    const float* W_z2p       = (const float*)d_in[17];
    const float* W_cq        = (const float*)d_in[18];
    const float* W_ck        = (const float*)d_in[19];
    const float* W1          = (const float*)d_in[20];
    const float* W2          = (const float*)d_in[21];
    const float* W3          = (const float*)d_in[22];
    const int*   uid         = (const int*)d_in[24];

    float* out   = (float*)d_out;
    float* q_out = out;
    float* c_out = out + (size_t)N_ATOMS * AS;
    float* p_out = out + (size_t)2 * N_ATOMS * AS;

    static cudaStream_t s_side = nullptr;
    static cudaEvent_t  e_fork = nullptr, e_join = nullptr;
    static bool s_init = false;
    if (!s_init) {
        s_init = true;
        if (cudaStreamCreateWithFlags(&s_side, cudaStreamNonBlocking) != cudaSuccess)
            s_side = nullptr;
        if (s_side) {
            if (cudaEventCreateWithFlags(&e_fork, cudaEventDisableTiming) != cudaSuccess ||
                cudaEventCreateWithFlags(&e_join, cudaEventDisableTiming) != cudaSuccess) {
                s_side = nullptr;
            }
        }
    }
    cudaFuncSetAttribute(zp_kernel,
                         cudaFuncAttributeMaxDynamicSharedMemorySize, ZP_SMEM);

    bool overlap = (s_side != nullptr);
    cudaStream_t sc = overlap ? s_side : (cudaStream_t)0;

    if (overlap) {
        cudaEventRecord(e_fork, 0);
        cudaStreamWaitEvent(sc, e_fork, 0);
    }

    // R10 launch order: prep + zp on s0, s2c + c on side (c profiled at #4)
    prep_kernel<<<1, 128>>>(ln_z_s, ln_z_b, W_z2p);                          // #1 s0
    zp_kernel  <<<T_TOK * T_TOK / 128, 128, ZP_SMEM>>>(z);                   // #2 s0
    s2c_kernel <<<T_TOK / 4, 128, 0, sc>>>(s_trunk, ln_s_s, ln_s_b, W_s2c);  // #3 side
    c_kernel   <<<N_ATOMS / 16, 256, 0, sc>>>(ref_pos, ref_charge, ref_element,
                                              ref_chars, W_feat, b_feat,
                                              W_cq, W_ck, uid, q_out, c_out); // #4 side
    if (overlap) {
        cudaEventRecord(e_join, sc);
        cudaStreamWaitEvent(0, e_join, 0);
    }
    pairs_kernel<<<N_ATOMS / 2, 128>>>(ref_pos, uid, W_rp, W_rd, W_msk,
                                       W1, W2, W3, p_out);                    // #5 s0
    (void)in_sizes; (void)n_in; (void)out_size;
}